// round 1
// baseline (speedup 1.0000x reference)
#include <cuda_runtime.h>

// ---------------------------------------------------------------------------
// Problem constants (shapes from reference)
// ---------------------------------------------------------------------------
#define NMAX 50000          // max users == max items
#define DIN  256
#define DHID 256
#define DOUT 128

// ---------------------------------------------------------------------------
// Device scratch (static __device__ globals: the allowed scratch mechanism)
// ---------------------------------------------------------------------------
__device__ float g_feat[(size_t)NMAX * DHID];   // GEMM output (reused per relation)
__device__ float g_aggA[(size_t)NMAX * DHID];   // scatter accumulator A
__device__ float g_aggB[(size_t)NMAX * DHID];   // scatter accumulator B
__device__ float g_hu  [(size_t)NMAX * DHID];   // layer-1 user hidden
__device__ float g_hi  [(size_t)NMAX * DHID];   // layer-1 item hidden
__device__ int   g_deg [6 * NMAX];              // degree counters (6 arrays)
__device__ float g_rsq [6 * NMAX];              // rsqrt(max(deg,1))

// slot layout in g_deg / g_rsq:
// 0: out-deg follows (users)   1: in-deg follows (users)
// 2: out-deg rates   (users)   3: in-deg rates   (items)
// 4: out-deg ratedby (items)   5: in-deg ratedby (users)

// ---------------------------------------------------------------------------
// Degree counting
// ---------------------------------------------------------------------------
__global__ void deg_kernel(const int* __restrict__ src, const int* __restrict__ dst,
                           int* __restrict__ degO, int* __restrict__ degI, int E)
{
    int i = blockIdx.x * blockDim.x + threadIdx.x;
    if (i < E) {
        atomicAdd(&degO[src[i]], 1);
        atomicAdd(&degI[dst[i]], 1);
    }
}

__global__ void rsq_kernel(const int* __restrict__ deg, float* __restrict__ rsq, int n)
{
    int i = blockIdx.x * blockDim.x + threadIdx.x;
    if (i < n) rsq[i] = rsqrtf(fmaxf((float)deg[i], 1.0f));
}

// ---------------------------------------------------------------------------
// Row-scaled SGEMM: C[M x N] = diag(scale) * A[M x 256] @ W[256 x N]
// BM=64, BN=64, BK=16, 256 threads, 4x4 per-thread tile.
// ---------------------------------------------------------------------------
template<int N>
__global__ __launch_bounds__(256)
void gemm_rowscale(const float* __restrict__ A, const float* __restrict__ W,
                   const float* __restrict__ scale, float* __restrict__ C, int M)
{
    constexpr int K = 256;
    constexpr int BM = 64, BN = 64, BK = 16;
    __shared__ float As[BK][BM];   // transposed A tile
    __shared__ float Bs[BK][BN];

    const int tid = threadIdx.x;
    const int tx = tid & 15;        // 0..15  -> column group
    const int ty = tid >> 4;        // 0..15  -> row group

    const int row0 = blockIdx.x * BM;
    const int col0 = blockIdx.y * BN;

    // A tile load mapping: thread -> (row within tile, float4 along K)
    const int arow  = tid >> 2;          // 0..63
    const int acol4 = (tid & 3) * 4;     // 0,4,8,12
    const int grow  = row0 + arow;
    const bool arow_ok = (grow < M);
    const float sc = arow_ok ? scale[grow] : 0.0f;
    const float4* Arow = (const float4*)(A + (size_t)grow * K);

    // B tile load mapping
    const int brow  = tid >> 4;          // 0..15
    const int bcol4 = (tid & 15) * 4;    // 0..60

    float c[4][4] = {};

    for (int k0 = 0; k0 < K; k0 += BK) {
        float4 av = arow_ok ? Arow[(k0 + acol4) >> 2] : make_float4(0.f, 0.f, 0.f, 0.f);
        As[acol4 + 0][arow] = av.x * sc;
        As[acol4 + 1][arow] = av.y * sc;
        As[acol4 + 2][arow] = av.z * sc;
        As[acol4 + 3][arow] = av.w * sc;

        float4 bv = *(const float4*)(W + (size_t)(k0 + brow) * N + col0 + bcol4);
        *(float4*)&Bs[brow][bcol4] = bv;

        __syncthreads();
        #pragma unroll
        for (int kk = 0; kk < BK; kk++) {
            float4 a4 = *(const float4*)&As[kk][ty * 4];
            float4 b4 = *(const float4*)&Bs[kk][tx * 4];
            float a[4] = {a4.x, a4.y, a4.z, a4.w};
            float b[4] = {b4.x, b4.y, b4.z, b4.w};
            #pragma unroll
            for (int i = 0; i < 4; i++)
                #pragma unroll
                for (int j = 0; j < 4; j++)
                    c[i][j] += a[i] * b[j];
        }
        __syncthreads();
    }

    #pragma unroll
    for (int i = 0; i < 4; i++) {
        int r = row0 + ty * 4 + i;
        if (r < M) {
            float4 v = make_float4(c[i][0], c[i][1], c[i][2], c[i][3]);
            *(float4*)(C + (size_t)r * N + col0 + tx * 4) = v;
        }
    }
}

// ---------------------------------------------------------------------------
// Edge scatter-add: agg[dst] += feat[src].  One warp per edge, vector RED.
// ---------------------------------------------------------------------------
template<int D>
__global__ __launch_bounds__(256)
void scatter_add(const float* __restrict__ feat, const int* __restrict__ src,
                 const int* __restrict__ dst, float* __restrict__ agg, int E)
{
    int w = (blockIdx.x * blockDim.x + threadIdx.x) >> 5;
    if (w >= E) return;
    const int lane = threadIdx.x & 31;
    const int s = __ldg(&src[w]);
    const int d = __ldg(&dst[w]);
    const float4* fs = (const float4*)(feat + (size_t)s * D);
    float4*       ad = (float4*)(agg + (size_t)d * D);
    #pragma unroll
    for (int c = 0; c < D / 128; c++) {
        int idx = c * 32 + lane;
        float4 v = fs[idx];
        asm volatile("red.global.add.v4.f32 [%0], {%1, %2, %3, %4};"
                     :: "l"(ad + idx), "f"(v.x), "f"(v.y), "f"(v.z), "f"(v.w)
                     : "memory");
    }
}

// ---------------------------------------------------------------------------
// Epilogues
// ---------------------------------------------------------------------------
template<int D, bool RELU>
__global__ void combine2(const float* __restrict__ aggA, const float* __restrict__ rA,
                         const float* __restrict__ bA,
                         const float* __restrict__ aggB, const float* __restrict__ rB,
                         const float* __restrict__ bB,
                         float* __restrict__ out, int Nn)
{
    int i = blockIdx.x * blockDim.x + threadIdx.x;
    int total = Nn * (D / 4);
    if (i >= total) return;
    int row  = i / (D / 4);
    int col4 = (i % (D / 4)) * 4;
    float ra = rA[row], rb = rB[row];
    float4 a  = *(const float4*)(aggA + (size_t)row * D + col4);
    float4 b  = *(const float4*)(aggB + (size_t)row * D + col4);
    float4 ba = *(const float4*)(bA + col4);
    float4 bb = *(const float4*)(bB + col4);
    float4 o;
    o.x = 0.5f * (a.x * ra + ba.x + b.x * rb + bb.x);
    o.y = 0.5f * (a.y * ra + ba.y + b.y * rb + bb.y);
    o.z = 0.5f * (a.z * ra + ba.z + b.z * rb + bb.z);
    o.w = 0.5f * (a.w * ra + ba.w + b.w * rb + bb.w);
    if (RELU) {
        o.x = fmaxf(o.x, 0.f); o.y = fmaxf(o.y, 0.f);
        o.z = fmaxf(o.z, 0.f); o.w = fmaxf(o.w, 0.f);
    }
    *(float4*)(out + (size_t)row * D + col4) = o;
}

template<int D, bool RELU>
__global__ void combine1(const float* __restrict__ agg, const float* __restrict__ r,
                         const float* __restrict__ b, float* __restrict__ out, int Nn)
{
    int i = blockIdx.x * blockDim.x + threadIdx.x;
    int total = Nn * (D / 4);
    if (i >= total) return;
    int row  = i / (D / 4);
    int col4 = (i % (D / 4)) * 4;
    float rr = r[row];
    float4 a  = *(const float4*)(agg + (size_t)row * D + col4);
    float4 bb = *(const float4*)(b + col4);
    float4 o;
    o.x = a.x * rr + bb.x;
    o.y = a.y * rr + bb.y;
    o.z = a.z * rr + bb.z;
    o.w = a.w * rr + bb.w;
    if (RELU) {
        o.x = fmaxf(o.x, 0.f); o.y = fmaxf(o.y, 0.f);
        o.z = fmaxf(o.z, 0.f); o.w = fmaxf(o.w, 0.f);
    }
    *(float4*)(out + (size_t)row * D + col4) = o;
}

// ---------------------------------------------------------------------------
// Launch
// ---------------------------------------------------------------------------
extern "C" void kernel_launch(void* const* d_in, const int* in_sizes, int n_in,
                              void* d_out, int out_size)
{
    const float* x_user = (const float*)d_in[0];
    const float* x_item = (const float*)d_in[1];
    const float* W1f  = (const float*)d_in[2];  const float* b1f  = (const float*)d_in[3];
    const float* W1r  = (const float*)d_in[4];  const float* b1r  = (const float*)d_in[5];
    const float* W1rb = (const float*)d_in[6];  const float* b1rb = (const float*)d_in[7];
    const float* W2f  = (const float*)d_in[8];  const float* b2f  = (const float*)d_in[9];
    const float* W2r  = (const float*)d_in[10]; const float* b2r  = (const float*)d_in[11];
    const float* W2rb = (const float*)d_in[12]; const float* b2rb = (const float*)d_in[13];
    const int* srcF  = (const int*)d_in[14]; const int* dstF  = (const int*)d_in[15];
    const int* srcR  = (const int*)d_in[16]; const int* dstR  = (const int*)d_in[17];
    const int* srcRB = (const int*)d_in[18]; const int* dstRB = (const int*)d_in[19];
    float* out = (float*)d_out;

    const int NU = in_sizes[0] / DIN;
    const int NI = in_sizes[1] / DIN;
    const int E  = in_sizes[14];

    float *p_feat, *p_aggA, *p_aggB, *p_hu, *p_hi, *p_rsq;
    int* p_deg;
    cudaGetSymbolAddress((void**)&p_feat, g_feat);
    cudaGetSymbolAddress((void**)&p_aggA, g_aggA);
    cudaGetSymbolAddress((void**)&p_aggB, g_aggB);
    cudaGetSymbolAddress((void**)&p_hu,   g_hu);
    cudaGetSymbolAddress((void**)&p_hi,   g_hi);
    cudaGetSymbolAddress((void**)&p_deg,  g_deg);
    cudaGetSymbolAddress((void**)&p_rsq,  g_rsq);

    const int TB = 256;
    const int degGrid  = (E + TB - 1) / TB;
    const int scatGrid = (E + 7) / 8;           // 8 warps/block, warp per edge

    // ---- degrees -> rsqrt ----
    cudaMemsetAsync(p_deg, 0, 6 * NMAX * sizeof(int));
    deg_kernel<<<degGrid, TB>>>(srcF,  dstF,  p_deg + 0 * NMAX, p_deg + 1 * NMAX, E);
    deg_kernel<<<degGrid, TB>>>(srcR,  dstR,  p_deg + 2 * NMAX, p_deg + 3 * NMAX, E);
    deg_kernel<<<degGrid, TB>>>(srcRB, dstRB, p_deg + 4 * NMAX, p_deg + 5 * NMAX, E);
    rsq_kernel<<<(6 * NMAX + TB - 1) / TB, TB>>>(p_deg, p_rsq, 6 * NMAX);

    dim3 g256u((NU + 63) / 64, DHID / 64);
    dim3 g256i((NI + 63) / 64, DHID / 64);
    dim3 g128u((NU + 63) / 64, DOUT / 64);
    dim3 g128i((NI + 63) / 64, DOUT / 64);

    // ================= Layer 1 =================
    // follows: users -> users
    gemm_rowscale<DHID><<<g256u, TB>>>(x_user, W1f, p_rsq + 0 * NMAX, p_feat, NU);
    cudaMemsetAsync(p_aggA, 0, (size_t)NU * DHID * sizeof(float));
    scatter_add<DHID><<<scatGrid, TB>>>(p_feat, srcF, dstF, p_aggA, E);

    // ratedby: items -> users
    gemm_rowscale<DHID><<<g256i, TB>>>(x_item, W1rb, p_rsq + 4 * NMAX, p_feat, NI);
    cudaMemsetAsync(p_aggB, 0, (size_t)NU * DHID * sizeof(float));
    scatter_add<DHID><<<scatGrid, TB>>>(p_feat, srcRB, dstRB, p_aggB, E);

    // h_u = relu(0.5*(aggA*rsqInF + b1f + aggB*rsqInRB + b1rb))
    combine2<DHID, true><<<((size_t)NU * (DHID/4) + TB - 1) / TB, TB>>>(
        p_aggA, p_rsq + 1 * NMAX, b1f, p_aggB, p_rsq + 5 * NMAX, b1rb, p_hu, NU);

    // rates: users -> items
    gemm_rowscale<DHID><<<g256u, TB>>>(x_user, W1r, p_rsq + 2 * NMAX, p_feat, NU);
    cudaMemsetAsync(p_aggA, 0, (size_t)NI * DHID * sizeof(float));
    scatter_add<DHID><<<scatGrid, TB>>>(p_feat, srcR, dstR, p_aggA, E);
    combine1<DHID, true><<<((size_t)NI * (DHID/4) + TB - 1) / TB, TB>>>(
        p_aggA, p_rsq + 3 * NMAX, b1r, p_hi, NI);

    // ================= Layer 2 =================
    // follows: h_u -> users
    gemm_rowscale<DOUT><<<g128u, TB>>>(p_hu, W2f, p_rsq + 0 * NMAX, p_feat, NU);
    cudaMemsetAsync(p_aggA, 0, (size_t)NU * DOUT * sizeof(float));
    scatter_add<DOUT><<<scatGrid, TB>>>(p_feat, srcF, dstF, p_aggA, E);

    // ratedby: h_i -> users
    gemm_rowscale<DOUT><<<g128i, TB>>>(p_hi, W2rb, p_rsq + 4 * NMAX, p_feat, NI);
    cudaMemsetAsync(p_aggB, 0, (size_t)NU * DOUT * sizeof(float));
    scatter_add<DOUT><<<scatGrid, TB>>>(p_feat, srcRB, dstRB, p_aggB, E);

    // o_u (no relu) -> out[0 : NU*DOUT)
    combine2<DOUT, false><<<((size_t)NU * (DOUT/4) + TB - 1) / TB, TB>>>(
        p_aggA, p_rsq + 1 * NMAX, b2f, p_aggB, p_rsq + 5 * NMAX, b2rb, out, NU);

    // rates: h_u -> items
    gemm_rowscale<DOUT><<<g128u, TB>>>(p_hu, W2r, p_rsq + 2 * NMAX, p_feat, NU);
    cudaMemsetAsync(p_aggA, 0, (size_t)NI * DOUT * sizeof(float));
    scatter_add<DOUT><<<scatGrid, TB>>>(p_feat, srcR, dstR, p_aggA, E);

    // o_i (no relu) -> out[NU*DOUT : )
    combine1<DOUT, false><<<((size_t)NI * (DOUT/4) + TB - 1) / TB, TB>>>(
        p_aggA, p_rsq + 3 * NMAX, b2r, out + (size_t)NU * DOUT, NI);
}

// round 6
// speedup vs baseline: 2.2396x; 2.2396x over previous
#include <cuda_runtime.h>
#include <cstdint>

// ---------------------------------------------------------------------------
// Problem constants
// ---------------------------------------------------------------------------
#define NMAX 50000
#define DIN  256
#define DHID 256
#define DOUT 128

// ---------------------------------------------------------------------------
// Device scratch
// ---------------------------------------------------------------------------
__device__ float g_feat[(size_t)NMAX * DHID];
__device__ float g_aggA[(size_t)NMAX * DHID];
__device__ float g_aggB[(size_t)NMAX * DHID];
__device__ float g_hu  [(size_t)NMAX * DHID];
__device__ float g_hi  [(size_t)NMAX * DHID];
__device__ int   g_deg [6 * NMAX];
__device__ float g_rsq [6 * NMAX];

// ---------------------------------------------------------------------------
// Degrees
// ---------------------------------------------------------------------------
__global__ void deg_kernel(const int* __restrict__ src, const int* __restrict__ dst,
                           int* __restrict__ degO, int* __restrict__ degI, int E)
{
    int i = blockIdx.x * blockDim.x + threadIdx.x;
    if (i < E) {
        atomicAdd(&degO[src[i]], 1);
        atomicAdd(&degI[dst[i]], 1);
    }
}

__global__ void rsq_kernel(const int* __restrict__ deg, float* __restrict__ rsq, int n)
{
    int i = blockIdx.x * blockDim.x + threadIdx.x;
    if (i < n) rsq[i] = rsqrtf(fmaxf((float)deg[i], 1.0f));
}

// ---------------------------------------------------------------------------
// TF32 tensor-core GEMM: C[M x N] = diag(scale) * A[M x 256] @ W[256 x N]
// BM=128, BN=64, BK=32. 256 threads = 8 warps (4 M x 2 N), warp tile 32x32.
// m16n8k8 tf32 mma. Conflict-free smem via pad: A stride 36 (banks 4m+k),
// B stride 72 (banks 8k+n).
// ---------------------------------------------------------------------------
__device__ __forceinline__ uint32_t f2tf32(float x)
{
    uint32_t r;
    asm("cvt.rna.tf32.f32 %0, %1;" : "=r"(r) : "f"(x));
    return r;
}

template<int N>
__global__ __launch_bounds__(256)
void gemm_tf32(const float* __restrict__ A, const float* __restrict__ W,
               const float* __restrict__ scale, float* __restrict__ C, int M)
{
    constexpr int K = 256;
    constexpr int BM = 128, BN = 64, BK = 32;
    constexpr int ASTR = BK + 4;   // 36
    constexpr int BSTR = BN + 8;   // 72
    __shared__ float As[BM][ASTR];
    __shared__ float Bs[BK][BSTR];

    const int tid  = threadIdx.x;
    const int warp = tid >> 5;
    const int lane = tid & 31;
    const int wm = (warp >> 1) * 32;   // 0,32,64,96
    const int wn = (warp & 1) * 32;    // 0,32

    const int row0 = blockIdx.x * BM;
    const int col0 = blockIdx.y * BN;

    // A global load mapping: 4 passes of 32 rows, each thread one float4
    const int ar  = tid >> 3;          // 0..31
    const int ac4 = (tid & 7) * 4;     // 0..28
    float        scv[4];
    const float4* aptr[4];
    bool         aok[4];
    #pragma unroll
    for (int p = 0; p < 4; p++) {
        int r = row0 + p * 32 + ar;
        aok[p]  = (r < M);
        scv[p]  = aok[p] ? scale[r] : 0.0f;
        aptr[p] = (const float4*)(A + (size_t)(aok[p] ? r : 0) * K);
    }

    // B global load mapping: 2 passes of 16 rows, each thread one float4
    const int br  = tid >> 4;          // 0..15
    const int bc4 = (tid & 15) * 4;    // 0..60

    float acc[2][4][4] = {};

    for (int k0 = 0; k0 < K; k0 += BK) {
        // ---- stage A (row-scaled, tf32-rounded) ----
        #pragma unroll
        for (int p = 0; p < 4; p++) {
            float4 v = aok[p] ? aptr[p][(k0 + ac4) >> 2]
                              : make_float4(0.f, 0.f, 0.f, 0.f);
            int rr = p * 32 + ar;
            As[rr][ac4 + 0] = __uint_as_float(f2tf32(v.x * scv[p]));
            As[rr][ac4 + 1] = __uint_as_float(f2tf32(v.y * scv[p]));
            As[rr][ac4 + 2] = __uint_as_float(f2tf32(v.z * scv[p]));
            As[rr][ac4 + 3] = __uint_as_float(f2tf32(v.w * scv[p]));
        }
        // ---- stage B ----
        #pragma unroll
        for (int p = 0; p < 2; p++) {
            int kr = p * 16 + br;
            float4 v = *(const float4*)(W + (size_t)(k0 + kr) * N + col0 + bc4);
            Bs[kr][bc4 + 0] = __uint_as_float(f2tf32(v.x));
            Bs[kr][bc4 + 1] = __uint_as_float(f2tf32(v.y));
            Bs[kr][bc4 + 2] = __uint_as_float(f2tf32(v.z));
            Bs[kr][bc4 + 3] = __uint_as_float(f2tf32(v.w));
        }
        __syncthreads();

        #pragma unroll
        for (int ks = 0; ks < BK; ks += 8) {
            uint32_t a[2][4];
            #pragma unroll
            for (int mt = 0; mt < 2; mt++) {
                int r = wm + mt * 16 + (lane >> 2);
                int c = ks + (lane & 3);
                a[mt][0] = __float_as_uint(As[r    ][c    ]);
                a[mt][1] = __float_as_uint(As[r + 8][c    ]);
                a[mt][2] = __float_as_uint(As[r    ][c + 4]);
                a[mt][3] = __float_as_uint(As[r + 8][c + 4]);
            }
            uint32_t b[4][2];
            #pragma unroll
            for (int nt = 0; nt < 4; nt++) {
                int c = wn + nt * 8 + (lane >> 2);
                b[nt][0] = __float_as_uint(Bs[ks     + (lane & 3)][c]);
                b[nt][1] = __float_as_uint(Bs[ks + 4 + (lane & 3)][c]);
            }
            #pragma unroll
            for (int mt = 0; mt < 2; mt++)
                #pragma unroll
                for (int nt = 0; nt < 4; nt++) {
                    asm volatile(
                        "mma.sync.aligned.m16n8k8.row.col.f32.tf32.tf32.f32 "
                        "{%0,%1,%2,%3}, {%4,%5,%6,%7}, {%8,%9}, {%0,%1,%2,%3};"
                        : "+f"(acc[mt][nt][0]), "+f"(acc[mt][nt][1]),
                          "+f"(acc[mt][nt][2]), "+f"(acc[mt][nt][3])
                        : "r"(a[mt][0]), "r"(a[mt][1]), "r"(a[mt][2]), "r"(a[mt][3]),
                          "r"(b[nt][0]), "r"(b[nt][1]));
                }
        }
        __syncthreads();
    }

    // ---- epilogue: write C ----
    #pragma unroll
    for (int mt = 0; mt < 2; mt++) {
        int r0g = row0 + wm + mt * 16 + (lane >> 2);
        int r1g = r0g + 8;
        #pragma unroll
        for (int nt = 0; nt < 4; nt++) {
            int cg = col0 + wn + nt * 8 + 2 * (lane & 3);
            if (r0g < M)
                *(float2*)(C + (size_t)r0g * N + cg) =
                    make_float2(acc[mt][nt][0], acc[mt][nt][1]);
            if (r1g < M)
                *(float2*)(C + (size_t)r1g * N + cg) =
                    make_float2(acc[mt][nt][2], acc[mt][nt][3]);
        }
    }
}

// ---------------------------------------------------------------------------
// Edge scatter-add: agg[dst] += feat[src]. One warp per edge, vector RED.
// ---------------------------------------------------------------------------
template<int D>
__global__ __launch_bounds__(256)
void scatter_add(const float* __restrict__ feat, const int* __restrict__ src,
                 const int* __restrict__ dst, float* __restrict__ agg, int E)
{
    int w = (blockIdx.x * blockDim.x + threadIdx.x) >> 5;
    if (w >= E) return;
    const int lane = threadIdx.x & 31;
    const int s = __ldg(&src[w]);
    const int d = __ldg(&dst[w]);
    const float4* fs = (const float4*)(feat + (size_t)s * D);
    float4*       ad = (float4*)(agg + (size_t)d * D);
    #pragma unroll
    for (int c = 0; c < D / 128; c++) {
        int idx = c * 32 + lane;
        float4 v = fs[idx];
        asm volatile("red.global.add.v4.f32 [%0], {%1, %2, %3, %4};"
                     :: "l"(ad + idx), "f"(v.x), "f"(v.y), "f"(v.z), "f"(v.w)
                     : "memory");
    }
}

// ---------------------------------------------------------------------------
// Epilogues
// ---------------------------------------------------------------------------
template<int D, bool RELU>
__global__ void combine2(const float* __restrict__ aggA, const float* __restrict__ rA,
                         const float* __restrict__ bA,
                         const float* __restrict__ aggB, const float* __restrict__ rB,
                         const float* __restrict__ bB,
                         float* __restrict__ out, int Nn)
{
    int i = blockIdx.x * blockDim.x + threadIdx.x;
    int total = Nn * (D / 4);
    if (i >= total) return;
    int row  = i / (D / 4);
    int col4 = (i % (D / 4)) * 4;
    float ra = rA[row], rb = rB[row];
    float4 a  = *(const float4*)(aggA + (size_t)row * D + col4);
    float4 b  = *(const float4*)(aggB + (size_t)row * D + col4);
    float4 ba = *(const float4*)(bA + col4);
    float4 bb = *(const float4*)(bB + col4);
    float4 o;
    o.x = 0.5f * (a.x * ra + ba.x + b.x * rb + bb.x);
    o.y = 0.5f * (a.y * ra + ba.y + b.y * rb + bb.y);
    o.z = 0.5f * (a.z * ra + ba.z + b.z * rb + bb.z);
    o.w = 0.5f * (a.w * ra + ba.w + b.w * rb + bb.w);
    if (RELU) {
        o.x = fmaxf(o.x, 0.f); o.y = fmaxf(o.y, 0.f);
        o.z = fmaxf(o.z, 0.f); o.w = fmaxf(o.w, 0.f);
    }
    *(float4*)(out + (size_t)row * D + col4) = o;
}

template<int D, bool RELU>
__global__ void combine1(const float* __restrict__ agg, const float* __restrict__ r,
                         const float* __restrict__ b, float* __restrict__ out, int Nn)
{
    int i = blockIdx.x * blockDim.x + threadIdx.x;
    int total = Nn * (D / 4);
    if (i >= total) return;
    int row  = i / (D / 4);
    int col4 = (i % (D / 4)) * 4;
    float rr = r[row];
    float4 a  = *(const float4*)(agg + (size_t)row * D + col4);
    float4 bb = *(const float4*)(b + col4);
    float4 o;
    o.x = a.x * rr + bb.x;
    o.y = a.y * rr + bb.y;
    o.z = a.z * rr + bb.z;
    o.w = a.w * rr + bb.w;
    if (RELU) {
        o.x = fmaxf(o.x, 0.f); o.y = fmaxf(o.y, 0.f);
        o.z = fmaxf(o.z, 0.f); o.w = fmaxf(o.w, 0.f);
    }
    *(float4*)(out + (size_t)row * D + col4) = o;
}

// ---------------------------------------------------------------------------
// Launch
// ---------------------------------------------------------------------------
extern "C" void kernel_launch(void* const* d_in, const int* in_sizes, int n_in,
                              void* d_out, int out_size)
{
    const float* x_user = (const float*)d_in[0];
    const float* x_item = (const float*)d_in[1];
    const float* W1f  = (const float*)d_in[2];  const float* b1f  = (const float*)d_in[3];
    const float* W1r  = (const float*)d_in[4];  const float* b1r  = (const float*)d_in[5];
    const float* W1rb = (const float*)d_in[6];  const float* b1rb = (const float*)d_in[7];
    const float* W2f  = (const float*)d_in[8];  const float* b2f  = (const float*)d_in[9];
    const float* W2r  = (const float*)d_in[10]; const float* b2r  = (const float*)d_in[11];
    const float* W2rb = (const float*)d_in[12]; const float* b2rb = (const float*)d_in[13];
    const int* srcF  = (const int*)d_in[14]; const int* dstF  = (const int*)d_in[15];
    const int* srcR  = (const int*)d_in[16]; const int* dstR  = (const int*)d_in[17];
    const int* srcRB = (const int*)d_in[18]; const int* dstRB = (const int*)d_in[19];
    float* out = (float*)d_out;

    const int NU = in_sizes[0] / DIN;
    const int NI = in_sizes[1] / DIN;
    const int E  = in_sizes[14];

    float *p_feat, *p_aggA, *p_aggB, *p_hu, *p_hi, *p_rsq;
    int* p_deg;
    cudaGetSymbolAddress((void**)&p_feat, g_feat);
    cudaGetSymbolAddress((void**)&p_aggA, g_aggA);
    cudaGetSymbolAddress((void**)&p_aggB, g_aggB);
    cudaGetSymbolAddress((void**)&p_hu,   g_hu);
    cudaGetSymbolAddress((void**)&p_hi,   g_hi);
    cudaGetSymbolAddress((void**)&p_deg,  g_deg);
    cudaGetSymbolAddress((void**)&p_rsq,  g_rsq);

    const int TB = 256;
    const int degGrid  = (E + TB - 1) / TB;
    const int scatGrid = (E + 7) / 8;

    // ---- degrees -> rsqrt ----
    cudaMemsetAsync(p_deg, 0, 6 * NMAX * sizeof(int));
    deg_kernel<<<degGrid, TB>>>(srcF,  dstF,  p_deg + 0 * NMAX, p_deg + 1 * NMAX, E);
    deg_kernel<<<degGrid, TB>>>(srcR,  dstR,  p_deg + 2 * NMAX, p_deg + 3 * NMAX, E);
    deg_kernel<<<degGrid, TB>>>(srcRB, dstRB, p_deg + 4 * NMAX, p_deg + 5 * NMAX, E);
    rsq_kernel<<<(6 * NMAX + TB - 1) / TB, TB>>>(p_deg, p_rsq, 6 * NMAX);

    dim3 g256u((NU + 127) / 128, DHID / 64);
    dim3 g256i((NI + 127) / 128, DHID / 64);
    dim3 g128u((NU + 127) / 128, DOUT / 64);
    dim3 g128i((NI + 127) / 128, DOUT / 64);

    // ================= Layer 1 =================
    gemm_tf32<DHID><<<g256u, TB>>>(x_user, W1f, p_rsq + 0 * NMAX, p_feat, NU);
    cudaMemsetAsync(p_aggA, 0, (size_t)NU * DHID * sizeof(float));
    scatter_add<DHID><<<scatGrid, TB>>>(p_feat, srcF, dstF, p_aggA, E);

    gemm_tf32<DHID><<<g256i, TB>>>(x_item, W1rb, p_rsq + 4 * NMAX, p_feat, NI);
    cudaMemsetAsync(p_aggB, 0, (size_t)NU * DHID * sizeof(float));
    scatter_add<DHID><<<scatGrid, TB>>>(p_feat, srcRB, dstRB, p_aggB, E);

    combine2<DHID, true><<<((size_t)NU * (DHID/4) + TB - 1) / TB, TB>>>(
        p_aggA, p_rsq + 1 * NMAX, b1f, p_aggB, p_rsq + 5 * NMAX, b1rb, p_hu, NU);

    gemm_tf32<DHID><<<g256u, TB>>>(x_user, W1r, p_rsq + 2 * NMAX, p_feat, NU);
    cudaMemsetAsync(p_aggA, 0, (size_t)NI * DHID * sizeof(float));
    scatter_add<DHID><<<scatGrid, TB>>>(p_feat, srcR, dstR, p_aggA, E);
    combine1<DHID, true><<<((size_t)NI * (DHID/4) + TB - 1) / TB, TB>>>(
        p_aggA, p_rsq + 3 * NMAX, b1r, p_hi, NI);

    // ================= Layer 2 =================
    gemm_tf32<DOUT><<<g128u, TB>>>(p_hu, W2f, p_rsq + 0 * NMAX, p_feat, NU);
    cudaMemsetAsync(p_aggA, 0, (size_t)NU * DOUT * sizeof(float));
    scatter_add<DOUT><<<scatGrid, TB>>>(p_feat, srcF, dstF, p_aggA, E);

    gemm_tf32<DOUT><<<g128i, TB>>>(p_hi, W2rb, p_rsq + 4 * NMAX, p_feat, NI);
    cudaMemsetAsync(p_aggB, 0, (size_t)NU * DOUT * sizeof(float));
    scatter_add<DOUT><<<scatGrid, TB>>>(p_feat, srcRB, dstRB, p_aggB, E);

    combine2<DOUT, false><<<((size_t)NU * (DOUT/4) + TB - 1) / TB, TB>>>(
        p_aggA, p_rsq + 1 * NMAX, b2f, p_aggB, p_rsq + 5 * NMAX, b2rb, out, NU);

    gemm_tf32<DOUT><<<g128u, TB>>>(p_hu, W2r, p_rsq + 2 * NMAX, p_feat, NU);
    cudaMemsetAsync(p_aggA, 0, (size_t)NI * DOUT * sizeof(float));
    scatter_add<DOUT><<<scatGrid, TB>>>(p_feat, srcR, dstR, p_aggA, E);

    combine1<DOUT, false><<<((size_t)NI * (DOUT/4) + TB - 1) / TB, TB>>>(
        p_aggA, p_rsq + 3 * NMAX, b2r, out + (size_t)NU * DOUT, NI);
}

// round 7
// speedup vs baseline: 3.7502x; 1.6745x over previous
#include <cuda_runtime.h>
#include <cstdint>

// ---------------------------------------------------------------------------
// Problem constants
// ---------------------------------------------------------------------------
#define NMAX 50000
#define EMAX 800000
#define DIN  256
#define DHID 256
#define DOUT 128

// ---------------------------------------------------------------------------
// Device scratch
// ---------------------------------------------------------------------------
__device__ float g_featA[(size_t)NMAX * DHID];
__device__ float g_featB[(size_t)NMAX * DHID];
__device__ float g_hu  [(size_t)NMAX * DHID];
__device__ float g_hi  [(size_t)NMAX * DHID];
__device__ int   g_deg [6 * NMAX];      // 0/2/4: out-deg F/R/RB, 1/3/5: in-deg F/R/RB
__device__ float g_rsq [6 * NMAX];
__device__ int   g_csr_ptr[3 * NMAX];   // per-relation dst row offsets (becomes END after place)
__device__ int   g_csr_src[3 * EMAX];   // src node ids grouped by dst

// ---------------------------------------------------------------------------
// Degrees (also the CSR histogram)
// ---------------------------------------------------------------------------
__global__ void deg_kernel(const int* __restrict__ src, const int* __restrict__ dst,
                           int* __restrict__ degO, int* __restrict__ degI, int E)
{
    int i = blockIdx.x * blockDim.x + threadIdx.x;
    if (i < E) {
        atomicAdd(&degO[src[i]], 1);
        atomicAdd(&degI[dst[i]], 1);
    }
}

__global__ void rsq_kernel(const int* __restrict__ deg, float* __restrict__ rsq, int n)
{
    int i = blockIdx.x * blockDim.x + threadIdx.x;
    if (i < n) rsq[i] = rsqrtf(fmaxf((float)deg[i], 1.0f));
}

// ---------------------------------------------------------------------------
// Exclusive scan of the 3 in-degree histograms -> csr_ptr. One block per rel.
// ---------------------------------------------------------------------------
__global__ __launch_bounds__(1024)
void scan3_kernel(const int* __restrict__ deg, int* __restrict__ csr_ptr)
{
    const int rel = blockIdx.x;
    const int* c = deg + (2 * rel + 1) * NMAX;
    int* p = csr_ptr + rel * NMAX;
    __shared__ int wtot[32];
    __shared__ int carry;
    const int tid = threadIdx.x, lane = tid & 31, wid = tid >> 5;
    if (tid == 0) carry = 0;
    __syncthreads();
    for (int base = 0; base < NMAX; base += 1024) {
        int i = base + tid;
        int v = (i < NMAX) ? c[i] : 0;
        int x = v;
        #pragma unroll
        for (int d = 1; d < 32; d <<= 1) {
            int y = __shfl_up_sync(0xffffffffu, x, d);
            if (lane >= d) x += y;
        }
        if (lane == 31) wtot[wid] = x;
        __syncthreads();
        if (wid == 0) {
            int t = wtot[lane];
            #pragma unroll
            for (int d = 1; d < 32; d <<= 1) {
                int y = __shfl_up_sync(0xffffffffu, t, d);
                if (lane >= d) t += y;
            }
            wtot[lane] = t;
        }
        __syncthreads();
        int base_w = (wid == 0) ? 0 : wtot[wid - 1];
        if (i < NMAX) p[i] = carry + base_w + x - v;
        __syncthreads();
        if (tid == 0) carry += wtot[31];
        __syncthreads();
    }
}

// ---------------------------------------------------------------------------
// CSR placement: after this, ptr[r] = END offset of row r (begin = end - deg).
// ---------------------------------------------------------------------------
__global__ void place_kernel(const int* __restrict__ src, const int* __restrict__ dst,
                             int* __restrict__ ptr, int* __restrict__ outsrc, int E)
{
    int i = blockIdx.x * blockDim.x + threadIdx.x;
    if (i < E) {
        int p = atomicAdd(&ptr[dst[i]], 1);
        outsrc[p] = src[i];
    }
}

// ---------------------------------------------------------------------------
// TF32 tensor-core GEMM: C[M x N] = diag(scale) * A[M x 256] @ W[256 x N]
// ---------------------------------------------------------------------------
__device__ __forceinline__ uint32_t f2tf32(float x)
{
    uint32_t r;
    asm("cvt.rna.tf32.f32 %0, %1;" : "=r"(r) : "f"(x));
    return r;
}

template<int N>
__global__ __launch_bounds__(256)
void gemm_tf32(const float* __restrict__ A, const float* __restrict__ W,
               const float* __restrict__ scale, float* __restrict__ C, int M)
{
    constexpr int K = 256;
    constexpr int BM = 128, BN = 64, BK = 32;
    constexpr int ASTR = BK + 4;   // 36
    constexpr int BSTR = BN + 8;   // 72
    __shared__ float As[BM][ASTR];
    __shared__ float Bs[BK][BSTR];

    const int tid  = threadIdx.x;
    const int warp = tid >> 5;
    const int lane = tid & 31;
    const int wm = (warp >> 1) * 32;
    const int wn = (warp & 1) * 32;

    const int row0 = blockIdx.x * BM;
    const int col0 = blockIdx.y * BN;

    const int ar  = tid >> 3;
    const int ac4 = (tid & 7) * 4;
    float        scv[4];
    const float4* aptr[4];
    bool         aok[4];
    #pragma unroll
    for (int p = 0; p < 4; p++) {
        int r = row0 + p * 32 + ar;
        aok[p]  = (r < M);
        scv[p]  = aok[p] ? scale[r] : 0.0f;
        aptr[p] = (const float4*)(A + (size_t)(aok[p] ? r : 0) * K);
    }

    const int br  = tid >> 4;
    const int bc4 = (tid & 15) * 4;

    float acc[2][4][4] = {};

    for (int k0 = 0; k0 < K; k0 += BK) {
        #pragma unroll
        for (int p = 0; p < 4; p++) {
            float4 v = aok[p] ? aptr[p][(k0 + ac4) >> 2]
                              : make_float4(0.f, 0.f, 0.f, 0.f);
            int rr = p * 32 + ar;
            As[rr][ac4 + 0] = __uint_as_float(f2tf32(v.x * scv[p]));
            As[rr][ac4 + 1] = __uint_as_float(f2tf32(v.y * scv[p]));
            As[rr][ac4 + 2] = __uint_as_float(f2tf32(v.z * scv[p]));
            As[rr][ac4 + 3] = __uint_as_float(f2tf32(v.w * scv[p]));
        }
        #pragma unroll
        for (int p = 0; p < 2; p++) {
            int kr = p * 16 + br;
            float4 v = *(const float4*)(W + (size_t)(k0 + kr) * N + col0 + bc4);
            Bs[kr][bc4 + 0] = __uint_as_float(f2tf32(v.x));
            Bs[kr][bc4 + 1] = __uint_as_float(f2tf32(v.y));
            Bs[kr][bc4 + 2] = __uint_as_float(f2tf32(v.z));
            Bs[kr][bc4 + 3] = __uint_as_float(f2tf32(v.w));
        }
        __syncthreads();

        #pragma unroll
        for (int ks = 0; ks < BK; ks += 8) {
            uint32_t a[2][4];
            #pragma unroll
            for (int mt = 0; mt < 2; mt++) {
                int r = wm + mt * 16 + (lane >> 2);
                int c = ks + (lane & 3);
                a[mt][0] = __float_as_uint(As[r    ][c    ]);
                a[mt][1] = __float_as_uint(As[r + 8][c    ]);
                a[mt][2] = __float_as_uint(As[r    ][c + 4]);
                a[mt][3] = __float_as_uint(As[r + 8][c + 4]);
            }
            uint32_t b[4][2];
            #pragma unroll
            for (int nt = 0; nt < 4; nt++) {
                int c = wn + nt * 8 + (lane >> 2);
                b[nt][0] = __float_as_uint(Bs[ks     + (lane & 3)][c]);
                b[nt][1] = __float_as_uint(Bs[ks + 4 + (lane & 3)][c]);
            }
            #pragma unroll
            for (int mt = 0; mt < 2; mt++)
                #pragma unroll
                for (int nt = 0; nt < 4; nt++) {
                    asm volatile(
                        "mma.sync.aligned.m16n8k8.row.col.f32.tf32.tf32.f32 "
                        "{%0,%1,%2,%3}, {%4,%5,%6,%7}, {%8,%9}, {%0,%1,%2,%3};"
                        : "+f"(acc[mt][nt][0]), "+f"(acc[mt][nt][1]),
                          "+f"(acc[mt][nt][2]), "+f"(acc[mt][nt][3])
                        : "r"(a[mt][0]), "r"(a[mt][1]), "r"(a[mt][2]), "r"(a[mt][3]),
                          "r"(b[nt][0]), "r"(b[nt][1]));
                }
        }
        __syncthreads();
    }

    #pragma unroll
    for (int mt = 0; mt < 2; mt++) {
        int r0g = row0 + wm + mt * 16 + (lane >> 2);
        int r1g = r0g + 8;
        #pragma unroll
        for (int nt = 0; nt < 4; nt++) {
            int cg = col0 + wn + nt * 8 + 2 * (lane & 3);
            if (r0g < M)
                *(float2*)(C + (size_t)r0g * N + cg) =
                    make_float2(acc[mt][nt][0], acc[mt][nt][1]);
            if (r1g < M)
                *(float2*)(C + (size_t)r1g * N + cg) =
                    make_float2(acc[mt][nt][2], acc[mt][nt][3]);
        }
    }
}

// ---------------------------------------------------------------------------
// Gather-SpMM with fused epilogue. One warp per dst row.
// out[r] = epi( rsqA[r]*sum_{e in rowA(r)} featA[srcA[e]] + biasA
//             [ + rsqB[r]*sum_{e in rowB(r)} featB[srcB[e]] + biasB, *0.5 ] )
// Row r of relation X spans [ptrX[r]-cntX[r], ptrX[r]) in csr_src.
// ---------------------------------------------------------------------------
template<int D, bool TWO, bool RELU>
__global__ __launch_bounds__(256)
void spmm_csr(const float* __restrict__ featA, const int* __restrict__ ptrA,
              const int* __restrict__ srcA, const int* __restrict__ cntA,
              const float* __restrict__ rsqA, const float* __restrict__ biasA,
              const float* __restrict__ featB, const int* __restrict__ ptrB,
              const int* __restrict__ srcB, const int* __restrict__ cntB,
              const float* __restrict__ rsqB, const float* __restrict__ biasB,
              float* __restrict__ out, int Nn)
{
    int r = (blockIdx.x * blockDim.x + threadIdx.x) >> 5;
    if (r >= Nn) return;
    const int lane = threadIdx.x & 31;
    constexpr int C = D / 128;      // float4s per lane (2 for 256, 1 for 128)

    float4 res[C];

    // ---- relation A ----
    {
        int end = __ldg(&ptrA[r]);
        int cnt = __ldg(&cntA[r]);
        float4 acc[C];
        #pragma unroll
        for (int c = 0; c < C; c++) acc[c] = make_float4(0.f, 0.f, 0.f, 0.f);
        for (int e = end - cnt; e < end; e++) {
            int s = __ldg(&srcA[e]);
            const float4* row = (const float4*)(featA + (size_t)s * D);
            #pragma unroll
            for (int c = 0; c < C; c++) {
                float4 v = __ldg(&row[c * 32 + lane]);
                acc[c].x += v.x; acc[c].y += v.y;
                acc[c].z += v.z; acc[c].w += v.w;
            }
        }
        float ra = __ldg(&rsqA[r]);
        #pragma unroll
        for (int c = 0; c < C; c++) {
            float4 b = __ldg((const float4*)biasA + c * 32 + lane);
            res[c].x = acc[c].x * ra + b.x;
            res[c].y = acc[c].y * ra + b.y;
            res[c].z = acc[c].z * ra + b.z;
            res[c].w = acc[c].w * ra + b.w;
        }
    }

    // ---- relation B (fused mean over 2 relations) ----
    if (TWO) {
        int end = __ldg(&ptrB[r]);
        int cnt = __ldg(&cntB[r]);
        float4 acc[C];
        #pragma unroll
        for (int c = 0; c < C; c++) acc[c] = make_float4(0.f, 0.f, 0.f, 0.f);
        for (int e = end - cnt; e < end; e++) {
            int s = __ldg(&srcB[e]);
            const float4* row = (const float4*)(featB + (size_t)s * D);
            #pragma unroll
            for (int c = 0; c < C; c++) {
                float4 v = __ldg(&row[c * 32 + lane]);
                acc[c].x += v.x; acc[c].y += v.y;
                acc[c].z += v.z; acc[c].w += v.w;
            }
        }
        float rb = __ldg(&rsqB[r]);
        #pragma unroll
        for (int c = 0; c < C; c++) {
            float4 b = __ldg((const float4*)biasB + c * 32 + lane);
            res[c].x = 0.5f * (res[c].x + acc[c].x * rb + b.x);
            res[c].y = 0.5f * (res[c].y + acc[c].y * rb + b.y);
            res[c].z = 0.5f * (res[c].z + acc[c].z * rb + b.z);
            res[c].w = 0.5f * (res[c].w + acc[c].w * rb + b.w);
        }
    }

    #pragma unroll
    for (int c = 0; c < C; c++) {
        if (RELU) {
            res[c].x = fmaxf(res[c].x, 0.f); res[c].y = fmaxf(res[c].y, 0.f);
            res[c].z = fmaxf(res[c].z, 0.f); res[c].w = fmaxf(res[c].w, 0.f);
        }
        ((float4*)(out + (size_t)r * D))[c * 32 + lane] = res[c];
    }
}

// ---------------------------------------------------------------------------
// Launch
// ---------------------------------------------------------------------------
extern "C" void kernel_launch(void* const* d_in, const int* in_sizes, int n_in,
                              void* d_out, int out_size)
{
    const float* x_user = (const float*)d_in[0];
    const float* x_item = (const float*)d_in[1];
    const float* W1f  = (const float*)d_in[2];  const float* b1f  = (const float*)d_in[3];
    const float* W1r  = (const float*)d_in[4];  const float* b1r  = (const float*)d_in[5];
    const float* W1rb = (const float*)d_in[6];  const float* b1rb = (const float*)d_in[7];
    const float* W2f  = (const float*)d_in[8];  const float* b2f  = (const float*)d_in[9];
    const float* W2r  = (const float*)d_in[10]; const float* b2r  = (const float*)d_in[11];
    const float* W2rb = (const float*)d_in[12]; const float* b2rb = (const float*)d_in[13];
    const int* srcF  = (const int*)d_in[14]; const int* dstF  = (const int*)d_in[15];
    const int* srcR  = (const int*)d_in[16]; const int* dstR  = (const int*)d_in[17];
    const int* srcRB = (const int*)d_in[18]; const int* dstRB = (const int*)d_in[19];
    float* out = (float*)d_out;

    const int NU = in_sizes[0] / DIN;
    const int NI = in_sizes[1] / DIN;
    const int E  = in_sizes[14];

    float *p_featA, *p_featB, *p_hu, *p_hi, *p_rsq;
    int *p_deg, *p_ptr, *p_src;
    cudaGetSymbolAddress((void**)&p_featA, g_featA);
    cudaGetSymbolAddress((void**)&p_featB, g_featB);
    cudaGetSymbolAddress((void**)&p_hu,    g_hu);
    cudaGetSymbolAddress((void**)&p_hi,    g_hi);
    cudaGetSymbolAddress((void**)&p_deg,   g_deg);
    cudaGetSymbolAddress((void**)&p_rsq,   g_rsq);
    cudaGetSymbolAddress((void**)&p_ptr,   g_csr_ptr);
    cudaGetSymbolAddress((void**)&p_src,   g_csr_src);

    const int TB = 256;
    const int eGrid = (E + TB - 1) / TB;

    // ---- histograms (degrees) ----
    cudaMemsetAsync(p_deg, 0, 6 * NMAX * sizeof(int));
    deg_kernel<<<eGrid, TB>>>(srcF,  dstF,  p_deg + 0 * NMAX, p_deg + 1 * NMAX, E);
    deg_kernel<<<eGrid, TB>>>(srcR,  dstR,  p_deg + 2 * NMAX, p_deg + 3 * NMAX, E);
    deg_kernel<<<eGrid, TB>>>(srcRB, dstRB, p_deg + 4 * NMAX, p_deg + 5 * NMAX, E);
    rsq_kernel<<<(6 * NMAX + TB - 1) / TB, TB>>>(p_deg, p_rsq, 6 * NMAX);

    // ---- CSR build (reused by both layers) ----
    scan3_kernel<<<3, 1024>>>(p_deg, p_ptr);
    place_kernel<<<eGrid, TB>>>(srcF,  dstF,  p_ptr + 0 * NMAX, p_src + 0 * EMAX, E);
    place_kernel<<<eGrid, TB>>>(srcR,  dstR,  p_ptr + 1 * NMAX, p_src + 1 * EMAX, E);
    place_kernel<<<eGrid, TB>>>(srcRB, dstRB, p_ptr + 2 * NMAX, p_src + 2 * EMAX, E);

    dim3 g256u((NU + 127) / 128, DHID / 64);
    dim3 g256i((NI + 127) / 128, DHID / 64);
    dim3 g128u((NU + 127) / 128, DOUT / 64);
    dim3 g128i((NI + 127) / 128, DOUT / 64);
    const int spmmU = (NU * 32 + TB - 1) / TB;
    const int spmmI = (NI * 32 + TB - 1) / TB;

    // ================= Layer 1 =================
    // users: follows (users->users) + ratedby (items->users), fused mean
    gemm_tf32<DHID><<<g256u, TB>>>(x_user, W1f,  p_rsq + 0 * NMAX, p_featA, NU);
    gemm_tf32<DHID><<<g256i, TB>>>(x_item, W1rb, p_rsq + 4 * NMAX, p_featB, NI);
    spmm_csr<DHID, true, true><<<spmmU, TB>>>(
        p_featA, p_ptr + 0 * NMAX, p_src + 0 * EMAX, p_deg + 1 * NMAX, p_rsq + 1 * NMAX, b1f,
        p_featB, p_ptr + 2 * NMAX, p_src + 2 * EMAX, p_deg + 5 * NMAX, p_rsq + 5 * NMAX, b1rb,
        p_hu, NU);

    // items: rates (users->items)
    gemm_tf32<DHID><<<g256u, TB>>>(x_user, W1r, p_rsq + 2 * NMAX, p_featA, NU);
    spmm_csr<DHID, false, true><<<spmmI, TB>>>(
        p_featA, p_ptr + 1 * NMAX, p_src + 1 * EMAX, p_deg + 3 * NMAX, p_rsq + 3 * NMAX, b1r,
        nullptr, nullptr, nullptr, nullptr, nullptr, nullptr,
        p_hi, NI);

    // ================= Layer 2 =================
    gemm_tf32<DOUT><<<g128u, TB>>>(p_hu, W2f,  p_rsq + 0 * NMAX, p_featA, NU);
    gemm_tf32<DOUT><<<g128i, TB>>>(p_hi, W2rb, p_rsq + 4 * NMAX, p_featB, NI);
    spmm_csr<DOUT, true, false><<<spmmU, TB>>>(
        p_featA, p_ptr + 0 * NMAX, p_src + 0 * EMAX, p_deg + 1 * NMAX, p_rsq + 1 * NMAX, b2f,
        p_featB, p_ptr + 2 * NMAX, p_src + 2 * EMAX, p_deg + 5 * NMAX, p_rsq + 5 * NMAX, b2rb,
        out, NU);

    gemm_tf32<DOUT><<<g128u, TB>>>(p_hu, W2r, p_rsq + 2 * NMAX, p_featA, NU);
    spmm_csr<DOUT, false, false><<<spmmI, TB>>>(
        p_featA, p_ptr + 1 * NMAX, p_src + 1 * EMAX, p_deg + 3 * NMAX, p_rsq + 3 * NMAX, b2r,
        nullptr, nullptr, nullptr, nullptr, nullptr, nullptr,
        out + (size_t)NU * DOUT, NI);
}